// round 7
// baseline (speedup 1.0000x reference)
#include <cuda_runtime.h>
#include <cstdint>

#define N_MAX 50000
#define M_MAX 800000
#define D 128
#define SCAN_BS 512

// Scratch — __device__ globals only (no allocs allowed).
__device__ __align__(16) static float g_bufA[N_MAX * D];   // x after input GEMM
__device__ __align__(16) static float g_xn[N_MAX * D];     // normalized layer input
__device__ __align__(16) static float g_c[N_MAX * D];      // current normalized routing state
__device__ __align__(16) static float g_cnew[N_MAX * D];   // layer output (unnormalized)
__device__ static int g_src[M_MAX];
__device__ static int g_trg[M_MAX];
__device__ static int g_deg[N_MAX];
__device__ static int g_cnt[N_MAX];
__device__ static int g_tmp[N_MAX];          // block-local exclusive scan
__device__ static int g_bsum[256];           // per-block sums
__device__ static int g_rowptr[N_MAX + 1];
__device__ static int g_adj[M_MAX];          // incoming-edge src ids grouped by trg
__device__ static int g_is64;

// ------------------------------------------------- dtype detect (int32 vs int64)
__global__ void detect_kernel(const int* __restrict__ p) {
    if (threadIdx.x == 0 && blockIdx.x == 0) {
        int any = 0;
        for (int i = 0; i < 256; i++) any |= p[2 * i + 1];
        g_is64 = (any == 0) ? 1 : 0;
    }
}

// ---------------------------------------------------------------- idx convert
__global__ void idx_kernel(const void* __restrict__ ei,
                           int* __restrict__ src, int* __restrict__ trg, int m) {
    int i = blockIdx.x * blockDim.x + threadIdx.x;
    if (i >= m) return;
    if (g_is64) {
        const long long* p = (const long long*)ei;
        src[i] = (int)p[i];
        trg[i] = (int)p[m + i];
    } else {
        const int* p = (const int*)ei;
        src[i] = p[i];
        trg[i] = p[m + i];
    }
}

// ---------------------------------------------------------------- CSR build
__global__ void hist_kernel(const int* __restrict__ trg, int* __restrict__ deg, int m) {
    int i = blockIdx.x * blockDim.x + threadIdx.x;
    if (i < m) atomicAdd(&deg[trg[i]], 1);
}

// Phase 1: per-block exclusive scan (Hillis-Steele) + block sum.
__global__ void scan_block_kernel(const int* __restrict__ deg, int* __restrict__ tmp,
                                  int* __restrict__ bsum, int n) {
    __shared__ int sm[SCAN_BS];
    int t = threadIdx.x;
    int i = blockIdx.x * SCAN_BS + t;
    int v = (i < n) ? deg[i] : 0;
    sm[t] = v;
    __syncthreads();
    for (int off = 1; off < SCAN_BS; off <<= 1) {
        int y = (t >= off) ? sm[t - off] : 0;
        __syncthreads();
        sm[t] += y;
        __syncthreads();
    }
    if (i < n) tmp[i] = sm[t] - v;              // exclusive
    if (t == SCAN_BS - 1) bsum[blockIdx.x] = sm[t];
}

// Phase 2: exclusive scan of block sums (nb <= 256), single block.
__global__ void scan_bsum_kernel(int* __restrict__ bsum, int nb) {
    __shared__ int sm[256];
    int t = threadIdx.x;
    int v = (t < nb) ? bsum[t] : 0;
    sm[t] = v;
    __syncthreads();
    for (int off = 1; off < 256; off <<= 1) {
        int y = (t >= off) ? sm[t - off] : 0;
        __syncthreads();
        sm[t] += y;
        __syncthreads();
    }
    if (t < nb) bsum[t] = sm[t] - v;            // exclusive
}

// Phase 3: rowptr[i] = tmp[i] + bsum[i/SCAN_BS]; rowptr[n] = m.
__global__ void scan_add_kernel(const int* __restrict__ tmp, const int* __restrict__ bsum,
                                int* __restrict__ rowptr, int n, int m) {
    int i = blockIdx.x * blockDim.x + threadIdx.x;
    if (i < n) rowptr[i] = tmp[i] + bsum[i / SCAN_BS];
    if (i == 0) rowptr[n] = m;
}

__global__ void scatter_kernel(const int* __restrict__ src, const int* __restrict__ trg,
                               const int* __restrict__ rowptr, int* __restrict__ cnt,
                               int* __restrict__ adj, int m) {
    int i = blockIdx.x * blockDim.x + threadIdx.x;
    if (i >= m) return;
    int tg = trg[i];
    int pos = rowptr[tg] + atomicAdd(&cnt[tg], 1);
    adj[pos] = src[i];
}

// ---------------------------------------------------------------- GEMM + bias
#define BM 32
__global__ void gemm_bias_kernel(const float* __restrict__ A,
                                 const float* __restrict__ W,
                                 const float* __restrict__ b,
                                 float* __restrict__ C, int n) {
    __shared__ float As[BM * D];
    int j = threadIdx.x;
    int row0 = blockIdx.x * BM;
    int nvalid = n - row0; if (nvalid > BM) nvalid = BM;

    const float4* A4 = (const float4*)(A + (size_t)row0 * D);
    float4* As4 = (float4*)As;
    for (int i = threadIdx.x; i < nvalid * (D / 4); i += blockDim.x) As4[i] = A4[i];
    __syncthreads();

    float acc[BM];
#pragma unroll
    for (int r = 0; r < BM; r++) acc[r] = 0.f;
    for (int k = 0; k < D; k++) {
        float w = W[k * D + j];
#pragma unroll
        for (int r = 0; r < BM; r++) acc[r] = fmaf(As[r * D + k], w, acc[r]);
    }
    float bj = b[j];
    for (int r = 0; r < nvalid; r++) C[(size_t)(row0 + r) * D + j] = acc[r] + bj;
}

// ------------------------------------------------------- channel normalize
__global__ void norm_kernel(const float* __restrict__ in, float* __restrict__ out, int n) {
    int gw = (blockIdx.x * blockDim.x + threadIdx.x) >> 5;
    if (gw >= n) return;
    int lane = threadIdx.x & 31;
    float4 v = *(const float4*)(in + (size_t)gw * D + lane * 4);
    float ss = v.x * v.x + v.y * v.y + v.z * v.z + v.w * v.w;
    ss += __shfl_xor_sync(0xffffffffu, ss, 1);
    ss += __shfl_xor_sync(0xffffffffu, ss, 2);
    ss += __shfl_xor_sync(0xffffffffu, ss, 4);
    float inv = 1.0f / fmaxf(sqrtf(ss), 1e-12f);
    *(float4*)(out + (size_t)gw * D + lane * 4) =
        make_float4(v.x * inv, v.y * inv, v.z * inv, v.w * inv);
}

// ------------------------------------------- fused routing iteration
// warp per target node v. lane l holds elems [4l,4l+4); channel k = l/8.
// After xor{1,2,4}, `part` is the logit p_k, uniform within each 8-lane group.
// Channel max via xor{8,16}; denominator via xor{8,16} on e = exp(part-mx).
template <bool DO_NORM>
__global__ void iter_kernel(const int* __restrict__ rowptr, const int* __restrict__ adj,
                            const float* __restrict__ xn, const float* __restrict__ c,
                            float* __restrict__ out, int n) {
    int v = (blockIdx.x * blockDim.x + threadIdx.x) >> 5;
    if (v >= n) return;
    int lane = threadIdx.x & 31;

    float4 cv = *(const float4*)(c + (size_t)v * D + lane * 4);
    float sv = cv.x + cv.y + cv.z + cv.w;
    int b = (lane & 7) * 4;
    float s0 = __shfl_sync(0xffffffffu, sv, b);
    float s1 = __shfl_sync(0xffffffffu, sv, b + 1);
    float s2 = __shfl_sync(0xffffffffu, sv, b + 2);
    float s3 = __shfl_sync(0xffffffffu, sv, b + 3);

    float4 acc = *(const float4*)(xn + (size_t)v * D + lane * 4);  // residual

    int beg = rowptr[v], end = rowptr[v + 1];
    int i = beg;

    // 2-edge software pipeline: both z gathers in flight before either shfl tree.
    for (; i + 1 < end; i += 2) {
        int sa = adj[i], sb = adj[i + 1];
        float4 za = *(const float4*)(xn + (size_t)sa * D + lane * 4);
        float4 zb = *(const float4*)(xn + (size_t)sb * D + lane * 4);

        float pa = za.x * s0 + za.y * s1 + za.z * s2 + za.w * s3;
        float pb = zb.x * s0 + zb.y * s1 + zb.z * s2 + zb.w * s3;
        pa += __shfl_xor_sync(0xffffffffu, pa, 1);
        pb += __shfl_xor_sync(0xffffffffu, pb, 1);
        pa += __shfl_xor_sync(0xffffffffu, pa, 2);
        pb += __shfl_xor_sync(0xffffffffu, pb, 2);
        pa += __shfl_xor_sync(0xffffffffu, pa, 4);
        pb += __shfl_xor_sync(0xffffffffu, pb, 4);

        float ma = fmaxf(pa, __shfl_xor_sync(0xffffffffu, pa, 8));
        float mb = fmaxf(pb, __shfl_xor_sync(0xffffffffu, pb, 8));
        ma = fmaxf(ma, __shfl_xor_sync(0xffffffffu, ma, 16));
        mb = fmaxf(mb, __shfl_xor_sync(0xffffffffu, mb, 16));

        float ea = __expf(pa - ma);
        float eb = __expf(pb - mb);
        float da = ea + __shfl_xor_sync(0xffffffffu, ea, 8);
        float db = eb + __shfl_xor_sync(0xffffffffu, eb, 8);
        da += __shfl_xor_sync(0xffffffffu, da, 16);
        db += __shfl_xor_sync(0xffffffffu, db, 16);

        float wa = __fdividef(ea, da);
        float wb = __fdividef(eb, db);
        acc.x = fmaf(wa, za.x, acc.x); acc.x = fmaf(wb, zb.x, acc.x);
        acc.y = fmaf(wa, za.y, acc.y); acc.y = fmaf(wb, zb.y, acc.y);
        acc.z = fmaf(wa, za.z, acc.z); acc.z = fmaf(wb, zb.z, acc.z);
        acc.w = fmaf(wa, za.w, acc.w); acc.w = fmaf(wb, zb.w, acc.w);
    }
    // remainder edge
    if (i < end) {
        int s = adj[i];
        float4 z = *(const float4*)(xn + (size_t)s * D + lane * 4);
        float part = z.x * s0 + z.y * s1 + z.z * s2 + z.w * s3;
        part += __shfl_xor_sync(0xffffffffu, part, 1);
        part += __shfl_xor_sync(0xffffffffu, part, 2);
        part += __shfl_xor_sync(0xffffffffu, part, 4);
        float m1 = fmaxf(part, __shfl_xor_sync(0xffffffffu, part, 8));
        float mx = fmaxf(m1, __shfl_xor_sync(0xffffffffu, m1, 16));
        float e = __expf(part - mx);
        float d1 = e + __shfl_xor_sync(0xffffffffu, e, 8);
        float den = d1 + __shfl_xor_sync(0xffffffffu, d1, 16);
        float w = __fdividef(e, den);
        acc.x = fmaf(w, z.x, acc.x);
        acc.y = fmaf(w, z.y, acc.y);
        acc.z = fmaf(w, z.z, acc.z);
        acc.w = fmaf(w, z.w, acc.w);
    }

    if (DO_NORM) {
        float ss = acc.x * acc.x + acc.y * acc.y + acc.z * acc.z + acc.w * acc.w;
        ss += __shfl_xor_sync(0xffffffffu, ss, 1);
        ss += __shfl_xor_sync(0xffffffffu, ss, 2);
        ss += __shfl_xor_sync(0xffffffffu, ss, 4);
        float inv = 1.0f / fmaxf(sqrtf(ss), 1e-12f);
        acc.x *= inv; acc.y *= inv; acc.z *= inv; acc.w *= inv;
    }
    *(float4*)(out + (size_t)v * D + lane * 4) = acc;
}

// ---------------------------------------------------------------- launch
extern "C" void kernel_launch(void* const* d_in, const int* in_sizes, int n_in,
                              void* d_out, int out_size) {
    const float* feat  = (const float*)d_in[0];
    const void*  ei    = d_in[1];
    const float* lin_w = (const float*)d_in[2];
    const float* lin_b = (const float*)d_in[3];
    const float* mlp_w = (const float*)d_in[4];
    const float* mlp_b = (const float*)d_in[5];

    int n = in_sizes[0] / D;
    int m = in_sizes[1] / 2;

    float *bufA, *xn, *c, *cnew;
    int *src, *trg, *deg, *cnt, *tmp, *bsum, *rowptr, *adj;
    cudaGetSymbolAddress((void**)&bufA,   g_bufA);
    cudaGetSymbolAddress((void**)&xn,     g_xn);
    cudaGetSymbolAddress((void**)&c,      g_c);
    cudaGetSymbolAddress((void**)&cnew,   g_cnew);
    cudaGetSymbolAddress((void**)&src,    g_src);
    cudaGetSymbolAddress((void**)&trg,    g_trg);
    cudaGetSymbolAddress((void**)&deg,    g_deg);
    cudaGetSymbolAddress((void**)&cnt,    g_cnt);
    cudaGetSymbolAddress((void**)&tmp,    g_tmp);
    cudaGetSymbolAddress((void**)&bsum,   g_bsum);
    cudaGetSymbolAddress((void**)&rowptr, g_rowptr);
    cudaGetSymbolAddress((void**)&adj,    g_adj);

    // ---- edge preprocessing + CSR build (once per call)
    detect_kernel<<<1, 32>>>((const int*)ei);
    idx_kernel<<<(m + 255) / 256, 256>>>(ei, src, trg, m);
    cudaMemsetAsync(deg, 0, (size_t)n * sizeof(int), 0);
    cudaMemsetAsync(cnt, 0, (size_t)n * sizeof(int), 0);
    hist_kernel<<<(m + 255) / 256, 256>>>(trg, deg, m);
    int nb = (n + SCAN_BS - 1) / SCAN_BS;
    scan_block_kernel<<<nb, SCAN_BS>>>(deg, tmp, bsum, n);
    scan_bsum_kernel<<<1, 256>>>(bsum, nb);
    scan_add_kernel<<<(n + 255) / 256, 256>>>(tmp, bsum, rowptr, n, m);
    scatter_kernel<<<(m + 255) / 256, 256>>>(src, trg, rowptr, cnt, adj, m);

    // ---- x = feat @ lin_w + lin_b
    gemm_bias_kernel<<<(n + BM - 1) / BM, 128>>>(feat, lin_w, lin_b, bufA, n);

    int node_blocks = (n * 32 + 255) / 256;  // warp per node
    size_t nbytes = (size_t)n * D * sizeof(float);

    const float* x_in = bufA;
    for (int layer = 0; layer < 2; layer++) {
        norm_kernel<<<node_blocks, 256>>>(x_in, xn, n);
        iter_kernel<true ><<<node_blocks, 256>>>(rowptr, adj, xn, xn, c, n);   // t=0 (c==xn)
        iter_kernel<true ><<<node_blocks, 256>>>(rowptr, adj, xn, c, c, n);    // t=1
        iter_kernel<false><<<node_blocks, 256>>>(rowptr, adj, xn, c, cnew, n); // t=2 raw
        x_in = cnew;
    }

    // out = x @ mlp_w + mlp_b
    gemm_bias_kernel<<<(n + BM - 1) / BM, 128>>>(cnew, mlp_w, mlp_b, (float*)d_out, n);
    // second tuple element: x
    if (out_size >= 2 * n * D)
        cudaMemcpyAsync((float*)d_out + (size_t)n * D, cnew, nbytes,
                        cudaMemcpyDeviceToDevice, 0);
}

// round 8
// speedup vs baseline: 1.2319x; 1.2319x over previous
#include <cuda_runtime.h>
#include <cstdint>

#define N_MAX 50000
#define M_MAX 800000
#define D 128
#define SCAN_BS 512

// Scratch — __device__ globals only (no allocs allowed).
__device__ __align__(16) static float g_bufA[N_MAX * D];   // x after input GEMM
__device__ __align__(16) static float g_xn[N_MAX * D];     // normalized layer input
__device__ __align__(16) static float g_c[N_MAX * D];      // current normalized routing state
__device__ __align__(16) static float g_cnew[N_MAX * D];   // layer output (unnormalized)
__device__ static int g_src[M_MAX];
__device__ static int g_trg[M_MAX];
__device__ static int g_deg[N_MAX];
__device__ static int g_cnt[N_MAX];
__device__ static int g_tmp[N_MAX];          // block-local exclusive scan
__device__ static int g_bsum[256];           // per-block sums
__device__ static int g_rowptr[N_MAX + 1];
__device__ static int g_adj[M_MAX];          // incoming-edge src ids grouped by trg
__device__ static int g_is64;

// ------------------------------------------------- dtype detect (int32 vs int64)
__global__ void detect_kernel(const int* __restrict__ p) {
    if (threadIdx.x == 0 && blockIdx.x == 0) {
        int any = 0;
        for (int i = 0; i < 256; i++) any |= p[2 * i + 1];
        g_is64 = (any == 0) ? 1 : 0;
    }
}

// ---------------------------------------------------------------- idx convert
__global__ void idx_kernel(const void* __restrict__ ei,
                           int* __restrict__ src, int* __restrict__ trg, int m) {
    int i = blockIdx.x * blockDim.x + threadIdx.x;
    if (i >= m) return;
    if (g_is64) {
        const long long* p = (const long long*)ei;
        src[i] = (int)p[i];
        trg[i] = (int)p[m + i];
    } else {
        const int* p = (const int*)ei;
        src[i] = p[i];
        trg[i] = p[m + i];
    }
}

// ---------------------------------------------------------------- CSR build
__global__ void hist_kernel(const int* __restrict__ trg, int* __restrict__ deg, int m) {
    int i = blockIdx.x * blockDim.x + threadIdx.x;
    if (i < m) atomicAdd(&deg[trg[i]], 1);
}

// Phase 1: per-block exclusive scan (Hillis-Steele) + block sum.
__global__ void scan_block_kernel(const int* __restrict__ deg, int* __restrict__ tmp,
                                  int* __restrict__ bsum, int n) {
    __shared__ int sm[SCAN_BS];
    int t = threadIdx.x;
    int i = blockIdx.x * SCAN_BS + t;
    int v = (i < n) ? deg[i] : 0;
    sm[t] = v;
    __syncthreads();
    for (int off = 1; off < SCAN_BS; off <<= 1) {
        int y = (t >= off) ? sm[t - off] : 0;
        __syncthreads();
        sm[t] += y;
        __syncthreads();
    }
    if (i < n) tmp[i] = sm[t] - v;              // exclusive
    if (t == SCAN_BS - 1) bsum[blockIdx.x] = sm[t];
}

// Phase 2: exclusive scan of block sums (nb <= 256), single block.
__global__ void scan_bsum_kernel(int* __restrict__ bsum, int nb) {
    __shared__ int sm[256];
    int t = threadIdx.x;
    int v = (t < nb) ? bsum[t] : 0;
    sm[t] = v;
    __syncthreads();
    for (int off = 1; off < 256; off <<= 1) {
        int y = (t >= off) ? sm[t - off] : 0;
        __syncthreads();
        sm[t] += y;
        __syncthreads();
    }
    if (t < nb) bsum[t] = sm[t] - v;            // exclusive
}

// Phase 3: rowptr[i] = tmp[i] + bsum[i/SCAN_BS]; rowptr[n] = m.
__global__ void scan_add_kernel(const int* __restrict__ tmp, const int* __restrict__ bsum,
                                int* __restrict__ rowptr, int n, int m) {
    int i = blockIdx.x * blockDim.x + threadIdx.x;
    if (i < n) rowptr[i] = tmp[i] + bsum[i / SCAN_BS];
    if (i == 0) rowptr[n] = m;
}

__global__ void scatter_kernel(const int* __restrict__ src, const int* __restrict__ trg,
                               const int* __restrict__ rowptr, int* __restrict__ cnt,
                               int* __restrict__ adj, int m) {
    int i = blockIdx.x * blockDim.x + threadIdx.x;
    if (i >= m) return;
    int tg = trg[i];
    int pos = rowptr[tg] + atomicAdd(&cnt[tg], 1);
    adj[pos] = src[i];
}

// ---------------------------------------------------------------- GEMM + bias
#define BM 32
__global__ void gemm_bias_kernel(const float* __restrict__ A,
                                 const float* __restrict__ W,
                                 const float* __restrict__ b,
                                 float* __restrict__ C, int n) {
    __shared__ float As[BM * D];
    int j = threadIdx.x;
    int row0 = blockIdx.x * BM;
    int nvalid = n - row0; if (nvalid > BM) nvalid = BM;

    const float4* A4 = (const float4*)(A + (size_t)row0 * D);
    float4* As4 = (float4*)As;
    for (int i = threadIdx.x; i < nvalid * (D / 4); i += blockDim.x) As4[i] = A4[i];
    __syncthreads();

    float acc[BM];
#pragma unroll
    for (int r = 0; r < BM; r++) acc[r] = 0.f;
    for (int k = 0; k < D; k++) {
        float w = W[k * D + j];
#pragma unroll
        for (int r = 0; r < BM; r++) acc[r] = fmaf(As[r * D + k], w, acc[r]);
    }
    float bj = b[j];
    for (int r = 0; r < nvalid; r++) C[(size_t)(row0 + r) * D + j] = acc[r] + bj;
}

// ------------------------------------------------------- channel normalize
__global__ void norm_kernel(const float* __restrict__ in, float* __restrict__ out, int n) {
    int gw = (blockIdx.x * blockDim.x + threadIdx.x) >> 5;
    if (gw >= n) return;
    int lane = threadIdx.x & 31;
    float4 v = *(const float4*)(in + (size_t)gw * D + lane * 4);
    float ss = v.x * v.x + v.y * v.y + v.z * v.z + v.w * v.w;
    ss += __shfl_xor_sync(0xffffffffu, ss, 1);
    ss += __shfl_xor_sync(0xffffffffu, ss, 2);
    ss += __shfl_xor_sync(0xffffffffu, ss, 4);
    float inv = 1.0f / fmaxf(sqrtf(ss), 1e-12f);
    *(float4*)(out + (size_t)gw * D + lane * 4) =
        make_float4(v.x * inv, v.y * inv, v.z * inv, v.w * inv);
}

// ------------------------------------------- fused routing iteration
// warp per target node v. lane l holds elems [4l,4l+4); channel k = l/8.
// R4-proven structure: wide softmax (fixed-lane broadcasts, independent exps),
// with the redundant 5th exp replaced by selects (e_own is one of e0..e3).
template <bool DO_NORM>
__global__ void iter_kernel(const int* __restrict__ rowptr, const int* __restrict__ adj,
                            const float* __restrict__ xn, const float* __restrict__ c,
                            float* __restrict__ out, int n) {
    int v = (blockIdx.x * blockDim.x + threadIdx.x) >> 5;
    if (v >= n) return;
    int lane = threadIdx.x & 31;
    int ch = lane >> 3;  // channel of this lane

    float4 cv = *(const float4*)(c + (size_t)v * D + lane * 4);
    float sv = cv.x + cv.y + cv.z + cv.w;
    int b = (lane & 7) * 4;
    float s0 = __shfl_sync(0xffffffffu, sv, b);
    float s1 = __shfl_sync(0xffffffffu, sv, b + 1);
    float s2 = __shfl_sync(0xffffffffu, sv, b + 2);
    float s3 = __shfl_sync(0xffffffffu, sv, b + 3);

    float4 acc = *(const float4*)(xn + (size_t)v * D + lane * 4);  // residual

    int beg = rowptr[v], end = rowptr[v + 1];
    for (int i = beg; i < end; i++) {
        int s = adj[i];  // uniform across warp (broadcast load)
        float4 z = *(const float4*)(xn + (size_t)s * D + lane * 4);
        float part = z.x * s0 + z.y * s1 + z.z * s2 + z.w * s3;
        part += __shfl_xor_sync(0xffffffffu, part, 1);
        part += __shfl_xor_sync(0xffffffffu, part, 2);
        part += __shfl_xor_sync(0xffffffffu, part, 4);
        float p0 = __shfl_sync(0xffffffffu, part, 0);
        float p1 = __shfl_sync(0xffffffffu, part, 8);
        float p2 = __shfl_sync(0xffffffffu, part, 16);
        float p3 = __shfl_sync(0xffffffffu, part, 24);
        float mx = fmaxf(fmaxf(p0, p1), fmaxf(p2, p3));
        float e0 = __expf(p0 - mx);
        float e1 = __expf(p1 - mx);
        float e2 = __expf(p2 - mx);
        float e3 = __expf(p3 - mx);
        float den = e0 + e1 + e2 + e3;
        float eo = (ch == 0) ? e0 : (ch == 1) ? e1 : (ch == 2) ? e2 : e3;
        float w = __fdividef(eo, den);
        acc.x = fmaf(w, z.x, acc.x);
        acc.y = fmaf(w, z.y, acc.y);
        acc.z = fmaf(w, z.z, acc.z);
        acc.w = fmaf(w, z.w, acc.w);
    }

    if (DO_NORM) {
        float ss = acc.x * acc.x + acc.y * acc.y + acc.z * acc.z + acc.w * acc.w;
        ss += __shfl_xor_sync(0xffffffffu, ss, 1);
        ss += __shfl_xor_sync(0xffffffffu, ss, 2);
        ss += __shfl_xor_sync(0xffffffffu, ss, 4);
        float inv = 1.0f / fmaxf(sqrtf(ss), 1e-12f);
        acc.x *= inv; acc.y *= inv; acc.z *= inv; acc.w *= inv;
    }
    *(float4*)(out + (size_t)v * D + lane * 4) = acc;
}

// ---------------------------------------------------------------- launch
extern "C" void kernel_launch(void* const* d_in, const int* in_sizes, int n_in,
                              void* d_out, int out_size) {
    const float* feat  = (const float*)d_in[0];
    const void*  ei    = d_in[1];
    const float* lin_w = (const float*)d_in[2];
    const float* lin_b = (const float*)d_in[3];
    const float* mlp_w = (const float*)d_in[4];
    const float* mlp_b = (const float*)d_in[5];

    int n = in_sizes[0] / D;
    int m = in_sizes[1] / 2;

    float *bufA, *xn, *c, *cnew;
    int *src, *trg, *deg, *cnt, *tmp, *bsum, *rowptr, *adj;
    cudaGetSymbolAddress((void**)&bufA,   g_bufA);
    cudaGetSymbolAddress((void**)&xn,     g_xn);
    cudaGetSymbolAddress((void**)&c,      g_c);
    cudaGetSymbolAddress((void**)&cnew,   g_cnew);
    cudaGetSymbolAddress((void**)&src,    g_src);
    cudaGetSymbolAddress((void**)&trg,    g_trg);
    cudaGetSymbolAddress((void**)&deg,    g_deg);
    cudaGetSymbolAddress((void**)&cnt,    g_cnt);
    cudaGetSymbolAddress((void**)&tmp,    g_tmp);
    cudaGetSymbolAddress((void**)&bsum,   g_bsum);
    cudaGetSymbolAddress((void**)&rowptr, g_rowptr);
    cudaGetSymbolAddress((void**)&adj,    g_adj);

    // ---- edge preprocessing + CSR build (once per call)
    detect_kernel<<<1, 32>>>((const int*)ei);
    idx_kernel<<<(m + 255) / 256, 256>>>(ei, src, trg, m);
    cudaMemsetAsync(deg, 0, (size_t)n * sizeof(int), 0);
    cudaMemsetAsync(cnt, 0, (size_t)n * sizeof(int), 0);
    hist_kernel<<<(m + 255) / 256, 256>>>(trg, deg, m);
    int nb = (n + SCAN_BS - 1) / SCAN_BS;
    scan_block_kernel<<<nb, SCAN_BS>>>(deg, tmp, bsum, n);
    scan_bsum_kernel<<<1, 256>>>(bsum, nb);
    scan_add_kernel<<<(n + 255) / 256, 256>>>(tmp, bsum, rowptr, n, m);
    scatter_kernel<<<(m + 255) / 256, 256>>>(src, trg, rowptr, cnt, adj, m);

    // ---- x = feat @ lin_w + lin_b
    gemm_bias_kernel<<<(n + BM - 1) / BM, 128>>>(feat, lin_w, lin_b, bufA, n);

    int node_blocks = (n * 32 + 255) / 256;  // warp per node
    size_t nbytes = (size_t)n * D * sizeof(float);

    const float* x_in = bufA;
    for (int layer = 0; layer < 2; layer++) {
        norm_kernel<<<node_blocks, 256>>>(x_in, xn, n);
        iter_kernel<true ><<<node_blocks, 256>>>(rowptr, adj, xn, xn, c, n);   // t=0 (c==xn)
        iter_kernel<true ><<<node_blocks, 256>>>(rowptr, adj, xn, c, c, n);    // t=1
        iter_kernel<false><<<node_blocks, 256>>>(rowptr, adj, xn, c, cnew, n); // t=2 raw
        x_in = cnew;
    }

    // out = x @ mlp_w + mlp_b
    gemm_bias_kernel<<<(n + BM - 1) / BM, 128>>>(cnew, mlp_w, mlp_b, (float*)d_out, n);
    // second tuple element: x
    if (out_size >= 2 * n * D)
        cudaMemcpyAsync((float*)d_out + (size_t)n * D, cnew, nbytes,
                        cudaMemcpyDeviceToDevice, 0);
}

// round 9
// speedup vs baseline: 1.4409x; 1.1697x over previous
#include <cuda_runtime.h>
#include <cstdint>

#define N_MAX 50000
#define M_MAX 800000
#define D 128
#define SCAN_BS 512

// Scratch — __device__ globals only (no allocs allowed).
__device__ __align__(16) static float g_bufA[N_MAX * D];   // x after input GEMM
__device__ __align__(16) static float g_xn[N_MAX * D];     // normalized layer input
__device__ __align__(16) static float g_c[N_MAX * D];      // current normalized routing state
__device__ __align__(16) static float g_cnew[N_MAX * D];   // layer output (unnormalized)
__device__ static int g_src[M_MAX];
__device__ static int g_trg[M_MAX];
__device__ static int g_deg[N_MAX];
__device__ static int g_cnt[N_MAX];
__device__ static int g_tmp[N_MAX];          // block-local exclusive scan
__device__ static int g_bsum[256];           // per-block sums
__device__ static int g_rowptr[N_MAX + 1];
__device__ static int g_adj[M_MAX];          // incoming-edge src ids grouped by trg
__device__ static int g_is64;

// ------------------------------------------------- dtype detect (int32 vs int64)
__global__ void detect_kernel(const int* __restrict__ p) {
    if (threadIdx.x == 0 && blockIdx.x == 0) {
        int any = 0;
        for (int i = 0; i < 256; i++) any |= p[2 * i + 1];
        g_is64 = (any == 0) ? 1 : 0;
    }
}

// ---------------------------------------------------------------- idx convert
__global__ void idx_kernel(const void* __restrict__ ei,
                           int* __restrict__ src, int* __restrict__ trg, int m) {
    int i = blockIdx.x * blockDim.x + threadIdx.x;
    if (i >= m) return;
    if (g_is64) {
        const long long* p = (const long long*)ei;
        src[i] = (int)p[i];
        trg[i] = (int)p[m + i];
    } else {
        const int* p = (const int*)ei;
        src[i] = p[i];
        trg[i] = p[m + i];
    }
}

// ---------------------------------------------------------------- CSR build
__global__ void hist_kernel(const int* __restrict__ trg, int* __restrict__ deg, int m) {
    int i = blockIdx.x * blockDim.x + threadIdx.x;
    if (i < m) atomicAdd(&deg[trg[i]], 1);
}

// Phase 1: per-block exclusive scan (Hillis-Steele) + block sum.
__global__ void scan_block_kernel(const int* __restrict__ deg, int* __restrict__ tmp,
                                  int* __restrict__ bsum, int n) {
    __shared__ int sm[SCAN_BS];
    int t = threadIdx.x;
    int i = blockIdx.x * SCAN_BS + t;
    int v = (i < n) ? deg[i] : 0;
    sm[t] = v;
    __syncthreads();
    for (int off = 1; off < SCAN_BS; off <<= 1) {
        int y = (t >= off) ? sm[t - off] : 0;
        __syncthreads();
        sm[t] += y;
        __syncthreads();
    }
    if (i < n) tmp[i] = sm[t] - v;              // exclusive
    if (t == SCAN_BS - 1) bsum[blockIdx.x] = sm[t];
}

// Phase 2: exclusive scan of block sums (nb <= 256), single block.
__global__ void scan_bsum_kernel(int* __restrict__ bsum, int nb) {
    __shared__ int sm[256];
    int t = threadIdx.x;
    int v = (t < nb) ? bsum[t] : 0;
    sm[t] = v;
    __syncthreads();
    for (int off = 1; off < 256; off <<= 1) {
        int y = (t >= off) ? sm[t - off] : 0;
        __syncthreads();
        sm[t] += y;
        __syncthreads();
    }
    if (t < nb) bsum[t] = sm[t] - v;            // exclusive
}

// Phase 3: rowptr[i] = tmp[i] + bsum[i/SCAN_BS]; rowptr[n] = m.
__global__ void scan_add_kernel(const int* __restrict__ tmp, const int* __restrict__ bsum,
                                int* __restrict__ rowptr, int n, int m) {
    int i = blockIdx.x * blockDim.x + threadIdx.x;
    if (i < n) rowptr[i] = tmp[i] + bsum[i / SCAN_BS];
    if (i == 0) rowptr[n] = m;
}

__global__ void scatter_kernel(const int* __restrict__ src, const int* __restrict__ trg,
                               const int* __restrict__ rowptr, int* __restrict__ cnt,
                               int* __restrict__ adj, int m) {
    int i = blockIdx.x * blockDim.x + threadIdx.x;
    if (i >= m) return;
    int tg = trg[i];
    int pos = rowptr[tg] + atomicAdd(&cnt[tg], 1);
    adj[pos] = src[i];
}

// ---------------------------------------------------------------- GEMM + bias
#define BM 32
__global__ void gemm_bias_kernel(const float* __restrict__ A,
                                 const float* __restrict__ W,
                                 const float* __restrict__ b,
                                 float* __restrict__ C, int n) {
    __shared__ float As[BM * D];
    int j = threadIdx.x;
    int row0 = blockIdx.x * BM;
    int nvalid = n - row0; if (nvalid > BM) nvalid = BM;

    const float4* A4 = (const float4*)(A + (size_t)row0 * D);
    float4* As4 = (float4*)As;
    for (int i = threadIdx.x; i < nvalid * (D / 4); i += blockDim.x) As4[i] = A4[i];
    __syncthreads();

    float acc[BM];
#pragma unroll
    for (int r = 0; r < BM; r++) acc[r] = 0.f;
    for (int k = 0; k < D; k++) {
        float w = W[k * D + j];
#pragma unroll
        for (int r = 0; r < BM; r++) acc[r] = fmaf(As[r * D + k], w, acc[r]);
    }
    float bj = b[j];
    for (int r = 0; r < nvalid; r++) C[(size_t)(row0 + r) * D + j] = acc[r] + bj;
}

// ------------------------------------------------------- channel normalize
__global__ void norm_kernel(const float* __restrict__ in, float* __restrict__ out, int n) {
    int gw = (blockIdx.x * blockDim.x + threadIdx.x) >> 5;
    if (gw >= n) return;
    int lane = threadIdx.x & 31;
    float4 v = *(const float4*)(in + (size_t)gw * D + lane * 4);
    float ss = v.x * v.x + v.y * v.y + v.z * v.z + v.w * v.w;
    ss += __shfl_xor_sync(0xffffffffu, ss, 1);
    ss += __shfl_xor_sync(0xffffffffu, ss, 2);
    ss += __shfl_xor_sync(0xffffffffu, ss, 4);
    float inv = 1.0f / fmaxf(sqrtf(ss), 1e-12f);
    *(float4*)(out + (size_t)gw * D + lane * 4) =
        make_float4(v.x * inv, v.y * inv, v.z * inv, v.w * inv);
}

// ------------------------------------------- fused routing iteration
// warp per target node v; TWO edges per warp-iteration (16 lanes each).
// Half h = lane>>4 handles edge beg+2j+h. Within a half:
//   ch = (lane&15)>>2  (channel), q = lane&3
//   lane owns elements d in [ch*32 + q*8, +8)  (their s-index a = d&31 = q*8+j)
// Logit reduce: xor{1,2}; channel max: xor{4,8}; denom: xor{4,8}.
// Residual xn[v] seeded into half 0 only; halves merged via xor16 at the end.
template <bool DO_NORM>
__global__ void iter_kernel(const int* __restrict__ rowptr, const int* __restrict__ adj,
                            const float* __restrict__ xn, const float* __restrict__ c,
                            float* __restrict__ out, int n) {
    int v = (blockIdx.x * blockDim.x + threadIdx.x) >> 5;
    if (v >= n) return;
    int lane = threadIdx.x & 31;
    int half = lane >> 4;
    int q = lane & 3;
    int ch = (lane & 15) >> 2;
    int dbase = ch * 32 + q * 8;

    // s[a] = sum of c[v][4a..4a+3]; lane a holds sv. Redistribute 8 per lane.
    float4 cv = *(const float4*)(c + (size_t)v * D + lane * 4);
    float sv = cv.x + cv.y + cv.z + cv.w;
    float sr[8];
#pragma unroll
    for (int j = 0; j < 8; j++)
        sr[j] = __shfl_sync(0xffffffffu, sv, q * 8 + j);

    // residual into half 0 only (merge would double-count otherwise)
    float4 a0 = make_float4(0.f, 0.f, 0.f, 0.f);
    float4 a1 = make_float4(0.f, 0.f, 0.f, 0.f);
    if (half == 0) {
        a0 = *(const float4*)(xn + (size_t)v * D + dbase);
        a1 = *(const float4*)(xn + (size_t)v * D + dbase + 4);
    }

    int beg = rowptr[v], end = rowptr[v + 1];
    int nit = (end - beg + 1) >> 1;
    for (int j = 0; j < nit; j++) {
        int e = beg + 2 * j + half;
        bool valid = (e < end);
        int s = adj[valid ? e : beg];
        const float* zp = xn + (size_t)s * D + dbase;
        float4 z0 = *(const float4*)(zp);
        float4 z1 = *(const float4*)(zp + 4);

        float p = z0.x * sr[0] + z0.y * sr[1] + z0.z * sr[2] + z0.w * sr[3]
                + z1.x * sr[4] + z1.y * sr[5] + z1.z * sr[6] + z1.w * sr[7];
        p += __shfl_xor_sync(0xffffffffu, p, 1);
        p += __shfl_xor_sync(0xffffffffu, p, 2);       // p = logit for channel ch
        float mx = fmaxf(p, __shfl_xor_sync(0xffffffffu, p, 4));
        mx = fmaxf(mx, __shfl_xor_sync(0xffffffffu, mx, 8));
        float ex = __expf(p - mx);
        float den = ex + __shfl_xor_sync(0xffffffffu, ex, 4);
        den += __shfl_xor_sync(0xffffffffu, den, 8);
        float w = valid ? __fdividef(ex, den) : 0.f;

        a0.x = fmaf(w, z0.x, a0.x);
        a0.y = fmaf(w, z0.y, a0.y);
        a0.z = fmaf(w, z0.z, a0.z);
        a0.w = fmaf(w, z0.w, a0.w);
        a1.x = fmaf(w, z1.x, a1.x);
        a1.y = fmaf(w, z1.y, a1.y);
        a1.z = fmaf(w, z1.z, a1.z);
        a1.w = fmaf(w, z1.w, a1.w);
    }

    // merge halves
    a0.x += __shfl_xor_sync(0xffffffffu, a0.x, 16);
    a0.y += __shfl_xor_sync(0xffffffffu, a0.y, 16);
    a0.z += __shfl_xor_sync(0xffffffffu, a0.z, 16);
    a0.w += __shfl_xor_sync(0xffffffffu, a0.w, 16);
    a1.x += __shfl_xor_sync(0xffffffffu, a1.x, 16);
    a1.y += __shfl_xor_sync(0xffffffffu, a1.y, 16);
    a1.z += __shfl_xor_sync(0xffffffffu, a1.z, 16);
    a1.w += __shfl_xor_sync(0xffffffffu, a1.w, 16);

    if (DO_NORM) {
        // channel ch spans 4 lanes (q=0..3) x 8 elems; reduce via xor{1,2}
        float ss = a0.x * a0.x + a0.y * a0.y + a0.z * a0.z + a0.w * a0.w
                 + a1.x * a1.x + a1.y * a1.y + a1.z * a1.z + a1.w * a1.w;
        ss += __shfl_xor_sync(0xffffffffu, ss, 1);
        ss += __shfl_xor_sync(0xffffffffu, ss, 2);
        float inv = 1.0f / fmaxf(sqrtf(ss), 1e-12f);
        a0.x *= inv; a0.y *= inv; a0.z *= inv; a0.w *= inv;
        a1.x *= inv; a1.y *= inv; a1.z *= inv; a1.w *= inv;
    }

    if (half == 0) {
        *(float4*)(out + (size_t)v * D + dbase)     = a0;
        *(float4*)(out + (size_t)v * D + dbase + 4) = a1;
    }
}

// ---------------------------------------------------------------- launch
extern "C" void kernel_launch(void* const* d_in, const int* in_sizes, int n_in,
                              void* d_out, int out_size) {
    const float* feat  = (const float*)d_in[0];
    const void*  ei    = d_in[1];
    const float* lin_w = (const float*)d_in[2];
    const float* lin_b = (const float*)d_in[3];
    const float* mlp_w = (const float*)d_in[4];
    const float* mlp_b = (const float*)d_in[5];

    int n = in_sizes[0] / D;
    int m = in_sizes[1] / 2;

    float *bufA, *xn, *c, *cnew;
    int *src, *trg, *deg, *cnt, *tmp, *bsum, *rowptr, *adj;
    cudaGetSymbolAddress((void**)&bufA,   g_bufA);
    cudaGetSymbolAddress((void**)&xn,     g_xn);
    cudaGetSymbolAddress((void**)&c,      g_c);
    cudaGetSymbolAddress((void**)&cnew,   g_cnew);
    cudaGetSymbolAddress((void**)&src,    g_src);
    cudaGetSymbolAddress((void**)&trg,    g_trg);
    cudaGetSymbolAddress((void**)&deg,    g_deg);
    cudaGetSymbolAddress((void**)&cnt,    g_cnt);
    cudaGetSymbolAddress((void**)&tmp,    g_tmp);
    cudaGetSymbolAddress((void**)&bsum,   g_bsum);
    cudaGetSymbolAddress((void**)&rowptr, g_rowptr);
    cudaGetSymbolAddress((void**)&adj,    g_adj);

    // ---- edge preprocessing + CSR build (once per call)
    detect_kernel<<<1, 32>>>((const int*)ei);
    idx_kernel<<<(m + 255) / 256, 256>>>(ei, src, trg, m);
    cudaMemsetAsync(deg, 0, (size_t)n * sizeof(int), 0);
    cudaMemsetAsync(cnt, 0, (size_t)n * sizeof(int), 0);
    hist_kernel<<<(m + 255) / 256, 256>>>(trg, deg, m);
    int nb = (n + SCAN_BS - 1) / SCAN_BS;
    scan_block_kernel<<<nb, SCAN_BS>>>(deg, tmp, bsum, n);
    scan_bsum_kernel<<<1, 256>>>(bsum, nb);
    scan_add_kernel<<<(n + 255) / 256, 256>>>(tmp, bsum, rowptr, n, m);
    scatter_kernel<<<(m + 255) / 256, 256>>>(src, trg, rowptr, cnt, adj, m);

    // ---- x = feat @ lin_w + lin_b
    gemm_bias_kernel<<<(n + BM - 1) / BM, 128>>>(feat, lin_w, lin_b, bufA, n);

    int node_blocks = (n * 32 + 255) / 256;  // warp per node
    size_t nbytes = (size_t)n * D * sizeof(float);

    const float* x_in = bufA;
    for (int layer = 0; layer < 2; layer++) {
        norm_kernel<<<node_blocks, 256>>>(x_in, xn, n);
        iter_kernel<true ><<<node_blocks, 256>>>(rowptr, adj, xn, xn, c, n);   // t=0 (c==xn)
        iter_kernel<true ><<<node_blocks, 256>>>(rowptr, adj, xn, c, c, n);    // t=1
        iter_kernel<false><<<node_blocks, 256>>>(rowptr, adj, xn, c, cnew, n); // t=2 raw
        x_in = cnew;
    }

    // out = x @ mlp_w + mlp_b
    gemm_bias_kernel<<<(n + BM - 1) / BM, 128>>>(cnew, mlp_w, mlp_b, (float*)d_out, n);
    // second tuple element: x
    if (out_size >= 2 * n * D)
        cudaMemcpyAsync((float*)d_out + (size_t)n * D, cnew, nbytes,
                        cudaMemcpyDeviceToDevice, 0);
}